// round 5
// baseline (speedup 1.0000x reference)
#include <cuda_runtime.h>

#define NN 500000
#define NE 1000000
#define NG 512

#define SCAN_BS 256
#define SCAN_ELEMS 2048                       // 256 threads * 8
#define SCAN_NBLK ((NN + SCAN_ELEMS - 1) / SCAN_ELEMS)   // 245

typedef unsigned long long u64;

// ---------------- scratch ----------------
__device__ int    g_cnt_out[NN];
__device__ int    g_cnt_in [NN];
__device__ float  g_ns     [NN];   // rsqrt(max(deg_out,1))
__device__ int    g_row_off[NN + 1];
__device__ int    g_cursor [NN];
__device__ int    g_csr_src[NE];
__device__ int    g_bsum [256];
__device__ int    g_bpref[256];
__device__ float4 g_h1[NN * 8];    // [N,32]
__device__ float4 g_hp[NN * 8];    // [N,32] relu(h1@Wpool+bpool)

// ---------------- f32x2 helpers ----------------
__device__ __forceinline__ u64 pack2(float a) {
    u64 r;
    asm("mov.b64 %0, {%1, %1};" : "=l"(r) : "f"(a));
    return r;
}
__device__ __forceinline__ void fma2(u64& d, u64 a, u64 b) {
    asm("fma.rn.f32x2 %0, %1, %2, %0;" : "+l"(d) : "l"(a), "l"(b));
}
__device__ __forceinline__ float2 unpack2(u64 v) {
    float2 f;
    asm("mov.b64 {%0, %1}, %2;" : "=f"(f.x), "=f"(f.y) : "l"(v));
    return f;
}

// ---------------- init ----------------
__global__ void k_init(float* __restrict__ out) {
    int i = blockIdx.x * blockDim.x + threadIdx.x;
    if (i < NN) { g_cnt_out[i] = 0; g_cnt_in[i] = 0; }
    if (i < NG * 64) out[i] = 0.f;
}

// ---------------- degree counts ----------------
__global__ void k_deg(const int* __restrict__ src, const int* __restrict__ dst) {
    int e = blockIdx.x * blockDim.x + threadIdx.x;
    if (e < NE) {
        atomicAdd(&g_cnt_out[src[e]], 1);
        atomicAdd(&g_cnt_in [dst[e]], 1);
    }
}

// ---------------- scan pass 1 ----------------
__global__ __launch_bounds__(SCAN_BS) void k_scan_bsum() {
    __shared__ int sred[SCAN_BS];
    int b = blockIdx.x, t = threadIdx.x;
    int base = b * SCAN_ELEMS + t * 8;
    int s = 0;
#pragma unroll
    for (int k = 0; k < 8; k++) {
        int idx = base + k;
        if (idx < NN) s += g_cnt_in[idx];
    }
    sred[t] = s;
    __syncthreads();
    for (int o = SCAN_BS / 2; o > 0; o >>= 1) {
        if (t < o) sred[t] += sred[t + o];
        __syncthreads();
    }
    if (t == 0) g_bsum[b] = sred[0];
}

// ---------------- scan pass 2 ----------------
__global__ __launch_bounds__(SCAN_BS) void k_scan_top() {
    __shared__ int s[SCAN_BS];
    int t = threadIdx.x;
    int v = (t < SCAN_NBLK) ? g_bsum[t] : 0;
    s[t] = v;
    __syncthreads();
    for (int o = 1; o < SCAN_BS; o <<= 1) {
        int u = (t >= o) ? s[t - o] : 0;
        __syncthreads();
        s[t] += u;
        __syncthreads();
    }
    if (t < SCAN_NBLK) g_bpref[t] = s[t] - v;
    if (t == 0) g_row_off[NN] = NE;
}

// ---------------- scan pass 3 (also computes g_ns) ----------------
__global__ __launch_bounds__(SCAN_BS) void k_scan_write() {
    __shared__ int sth[SCAN_BS];
    int b = blockIdx.x, t = threadIdx.x;
    int base = b * SCAN_ELEMS + t * 8;
    int vals[8];
    int s = 0;
#pragma unroll
    for (int k = 0; k < 8; k++) {
        int idx = base + k;
        vals[k] = (idx < NN) ? g_cnt_in[idx] : 0;
        s += vals[k];
    }
    sth[t] = s;
    __syncthreads();
    int incl = s;
    for (int o = 1; o < SCAN_BS; o <<= 1) {
        int u = (t >= o) ? sth[t - o] : 0;
        __syncthreads();
        incl += u;
        sth[t] = incl;
        __syncthreads();
    }
    int run = g_bpref[b] + incl - s;
#pragma unroll
    for (int k = 0; k < 8; k++) {
        int idx = base + k;
        if (idx < NN) {
            g_row_off[idx] = run;
            g_cursor[idx] = run;
            g_ns[idx] = rsqrtf(fmaxf((float)g_cnt_out[idx], 1.0f));
        }
        run += vals[k];
    }
}

// ---------------- CSR fill ----------------
__global__ void k_fill(const int* __restrict__ src, const int* __restrict__ dst) {
    int e = blockIdx.x * blockDim.x + threadIdx.x;
    if (e < NE) {
        int p = atomicAdd(&g_cursor[dst[e]], 1);
        g_csr_src[p] = src[e];
    }
}

// ---------------- gather embed directly + MLP1 + pool MLP ----------------
__global__ __launch_bounds__(256) void k_h1(
    const int* __restrict__ tokens, const float* __restrict__ embed,
    const float* __restrict__ W1, const float* __restrict__ b1,
    const float* __restrict__ Wp, const float* __restrict__ bp)
{
    __shared__ __align__(16) u64 sW1[16 * 16], sWp[32 * 16];
    __shared__ u64 sb1[16], sbp[16];
    for (int t = threadIdx.x; t < 16 * 16; t += blockDim.x)
        ((float2*)sW1)[t] = ((const float2*)W1)[t];
    for (int t = threadIdx.x; t < 32 * 16; t += blockDim.x)
        ((float2*)sWp)[t] = ((const float2*)Wp)[t];
    for (int t = threadIdx.x; t < 16; t += blockDim.x) {
        ((float2*)sb1)[t] = ((const float2*)b1)[t];
        ((float2*)sbp)[t] = ((const float2*)bp)[t];
    }
    __syncthreads();

    int i = blockIdx.x * blockDim.x + threadIdx.x;
    if (i >= NN) return;

    int beg = g_row_off[i], end = g_row_off[i + 1];
    float4 a0 = make_float4(0, 0, 0, 0), a1 = a0, a2 = a0, a3 = a0;
    for (int e = beg; e < end; e++) {
        int s = g_csr_src[e];
        float ns = g_ns[s];
        const float4* er = (const float4*)(embed + (long)tokens[s] * 16);
        float4 v0 = er[0], v1 = er[1], v2 = er[2], v3 = er[3];
        a0.x += v0.x * ns; a0.y += v0.y * ns; a0.z += v0.z * ns; a0.w += v0.w * ns;
        a1.x += v1.x * ns; a1.y += v1.y * ns; a1.z += v1.z * ns; a1.w += v1.w * ns;
        a2.x += v2.x * ns; a2.y += v2.y * ns; a2.z += v2.z * ns; a2.w += v2.w * ns;
        a3.x += v3.x * ns; a3.y += v3.y * ns; a3.z += v3.z * ns; a3.w += v3.w * ns;
    }
    float nd = rsqrtf(fmaxf((float)(end - beg), 1.0f));
    float mr[16] = {a0.x * nd, a0.y * nd, a0.z * nd, a0.w * nd,
                    a1.x * nd, a1.y * nd, a1.z * nd, a1.w * nd,
                    a2.x * nd, a2.y * nd, a2.z * nd, a2.w * nd,
                    a3.x * nd, a3.y * nd, a3.z * nd, a3.w * nd};

    // h1 = relu(mr @ W1 + b1)
    u64 acc[16];
#pragma unroll
    for (int j = 0; j < 16; j++) acc[j] = sb1[j];
#pragma unroll
    for (int k = 0; k < 16; k++) {
        u64 av = pack2(mr[k]);
        const ulonglong2* pw = (const ulonglong2*)&sW1[k * 16];
#pragma unroll
        for (int jj = 0; jj < 8; jj++) {
            ulonglong2 w = pw[jj];
            fma2(acc[2 * jj], av, w.x);
            fma2(acc[2 * jj + 1], av, w.y);
        }
    }
    float h1f[32];
#pragma unroll
    for (int j = 0; j < 16; j++) {
        float2 f = unpack2(acc[j]);
        h1f[2 * j] = fmaxf(f.x, 0.f); h1f[2 * j + 1] = fmaxf(f.y, 0.f);
    }
#pragma unroll
    for (int k = 0; k < 8; k++)
        g_h1[i * 8 + k] = make_float4(h1f[4 * k], h1f[4 * k + 1], h1f[4 * k + 2], h1f[4 * k + 3]);

    // hp = relu(h1 @ Wpool + bpool)
    u64 pcc[16];
#pragma unroll
    for (int j = 0; j < 16; j++) pcc[j] = sbp[j];
#pragma unroll
    for (int k = 0; k < 32; k++) {
        u64 av = pack2(h1f[k]);
        const ulonglong2* pw = (const ulonglong2*)&sWp[k * 16];
#pragma unroll
        for (int jj = 0; jj < 8; jj++) {
            ulonglong2 w = pw[jj];
            fma2(pcc[2 * jj], av, w.x);
            fma2(pcc[2 * jj + 1], av, w.y);
        }
    }
#pragma unroll
    for (int j = 0; j < 8; j++) {
        float2 f0 = unpack2(pcc[2 * j]), f1 = unpack2(pcc[2 * j + 1]);
        g_hp[i * 8 + j] = make_float4(fmaxf(f0.x, 0.f), fmaxf(f0.y, 0.f),
                                      fmaxf(f1.x, 0.f), fmaxf(f1.y, 0.f));
    }
}

// ---------------- fused: gather-max + SAGE + lin + pooling (2 threads/node) ----------------
// even lane of a pair computes outputs 0-31, odd lane outputs 32-63
__global__ __launch_bounds__(256, 2) void k_out(
    const int* __restrict__ graph_ids,
    const float* __restrict__ Wself, const float* __restrict__ Wneigh,
    const float* __restrict__ bneigh,
    const float* __restrict__ Wlin, const float* __restrict__ blin,
    float* __restrict__ out)
{
    __shared__ __align__(16) u64 sWs[32 * 32], sWn[32 * 32], sWl[64 * 32];
    __shared__ u64 sbn[32], sbl[32];
    for (int t = threadIdx.x; t < 32 * 32; t += blockDim.x) {
        ((float2*)sWs)[t] = ((const float2*)Wself)[t];
        ((float2*)sWn)[t] = ((const float2*)Wneigh)[t];
    }
    for (int t = threadIdx.x; t < 64 * 32; t += blockDim.x)
        ((float2*)sWl)[t] = ((const float2*)Wlin)[t];
    for (int t = threadIdx.x; t < 32; t += blockDim.x) {
        ((float2*)sbn)[t] = ((const float2*)bneigh)[t];
        ((float2*)sbl)[t] = ((const float2*)blin)[t];
    }
    __syncthreads();

    int tid = threadIdx.x;
    int h = tid & 1;                              // which half of outputs/channels
    int node = blockIdx.x * 128 + (tid >> 1);
    bool valid = node < NN;
    int ic = valid ? node : NN - 1;
    int gid = graph_ids[ic];

    // each thread gathers HALF the channels (16) of af and hnf
    float mya[16], myn[16];
#pragma unroll
    for (int k = 0; k < 4; k++) {
        float4 v = g_h1[(size_t)ic * 8 + 4 * h + k];
        mya[4 * k + 0] = v.x; mya[4 * k + 1] = v.y; mya[4 * k + 2] = v.z; mya[4 * k + 3] = v.w;
        myn[4 * k + 0] = 0.f; myn[4 * k + 1] = 0.f; myn[4 * k + 2] = 0.f; myn[4 * k + 3] = 0.f;
    }
    int beg = g_row_off[ic], end = g_row_off[ic + 1];
    for (int e = beg; e < end; e++) {
        const float4* hr = &g_hp[(size_t)g_csr_src[e] * 8 + 4 * h];
#pragma unroll
        for (int k = 0; k < 4; k++) {
            float4 v = hr[k];
            myn[4 * k + 0] = fmaxf(myn[4 * k + 0], v.x);
            myn[4 * k + 1] = fmaxf(myn[4 * k + 1], v.y);
            myn[4 * k + 2] = fmaxf(myn[4 * k + 2], v.z);
            myn[4 * k + 3] = fmaxf(myn[4 * k + 3], v.w);
        }
    }

    // exchange halves within lane pair -> full 32-channel af/hnf
    float af[32], hnf[32];
#pragma unroll
    for (int j = 0; j < 16; j++) {
        float oa = __shfl_xor_sync(0xffffffffu, mya[j], 1);
        float on = __shfl_xor_sync(0xffffffffu, myn[j], 1);
        af[16 * h + j] = mya[j];
        af[16 * (1 - h) + j] = oa;
        hnf[16 * h + j] = myn[j];
        hnf[16 * (1 - h) + j] = on;
    }

    // h2 half: this thread's 32 outputs [32h .. 32h+31]
    u64 acc[16];
#pragma unroll
    for (int j = 0; j < 16; j++) acc[j] = sbn[16 * h + j];
#pragma unroll
    for (int k = 0; k < 32; k++) {
        u64 av = pack2(af[k]);
        u64 bv = pack2(hnf[k]);
        const ulonglong2* ps = (const ulonglong2*)&sWs[k * 32 + 16 * h];
        const ulonglong2* pn = (const ulonglong2*)&sWn[k * 32 + 16 * h];
#pragma unroll
        for (int jj = 0; jj < 8; jj++) {
            ulonglong2 w = ps[jj];
            fma2(acc[2 * jj], av, w.x);
            fma2(acc[2 * jj + 1], av, w.y);
            ulonglong2 u = pn[jj];
            fma2(acc[2 * jj], bv, u.x);
            fma2(acc[2 * jj + 1], bv, u.y);
        }
    }
    float hh[32];
#pragma unroll
    for (int j = 0; j < 16; j++) {
        float2 f = unpack2(acc[j]);
        hh[2 * j] = fmaxf(f.x, 0.f); hh[2 * j + 1] = fmaxf(f.y, 0.f);
    }

    // h3 half: own h2 half first, then partner's half streamed via shfl
    u64 h3acc[16];
#pragma unroll
    for (int j = 0; j < 16; j++) h3acc[j] = sbl[16 * h + j];
#pragma unroll
    for (int k2 = 0; k2 < 32; k2++) {
        u64 av = pack2(hh[k2]);
        const ulonglong2* pl = (const ulonglong2*)&sWl[(32 * h + k2) * 32 + 16 * h];
#pragma unroll
        for (int jj = 0; jj < 8; jj++) {
            ulonglong2 w = pl[jj];
            fma2(h3acc[2 * jj], av, w.x);
            fma2(h3acc[2 * jj + 1], av, w.y);
        }
    }
#pragma unroll
    for (int k2 = 0; k2 < 32; k2++) {
        float pv = __shfl_xor_sync(0xffffffffu, hh[k2], 1);
        u64 av = pack2(pv);
        const ulonglong2* pl = (const ulonglong2*)&sWl[(32 * (1 - h) + k2) * 32 + 16 * h];
#pragma unroll
        for (int jj = 0; jj < 8; jj++) {
            ulonglong2 w = pl[jj];
            fma2(h3acc[2 * jj], av, w.x);
            fma2(h3acc[2 * jj + 1], av, w.y);
        }
    }

    float v[32];
#pragma unroll
    for (int j = 0; j < 16; j++) {
        float2 f = unpack2(h3acc[j]);
        v[2 * j]     = valid ? fmaxf(f.x, 0.f) : 0.f;
        v[2 * j + 1] = valid ? fmaxf(f.y, 0.f) : 0.f;
    }

    // pooling: warp covers 16 nodes; graph_ids sorted -> warps almost always uniform
    int lane = tid & 31;
    int g0 = __shfl_sync(0xffffffffu, gid, 0);
    bool uni = __all_sync(0xffffffffu, gid == g0);
    if (uni) {
        // reduce across the 16 same-parity lanes (offsets 2,4,8,16 preserve parity)
#pragma unroll
        for (int j = 0; j < 32; j++) {
            float x = v[j];
            x += __shfl_xor_sync(0xffffffffu, x, 2);
            x += __shfl_xor_sync(0xffffffffu, x, 4);
            x += __shfl_xor_sync(0xffffffffu, x, 8);
            x += __shfl_xor_sync(0xffffffffu, x, 16);
            v[j] = x;
        }
        int p = lane >> 1;   // 0..15
        atomicAdd(out + g0 * 64 + 32 * h + 2 * p,     v[2 * p]);
        atomicAdd(out + g0 * 64 + 32 * h + 2 * p + 1, v[2 * p + 1]);
    } else if (valid) {
        float* row = out + gid * 64 + 32 * h;
#pragma unroll
        for (int j = 0; j < 32; j++) atomicAdd(row + j, v[j]);
    }
}

// ---------------- launch ----------------
extern "C" void kernel_launch(void* const* d_in, const int* in_sizes, int n_in,
                              void* d_out, int out_size) {
    const int*   tokens    = (const int*)  d_in[0];
    const int*   edge_src  = (const int*)  d_in[1];
    const int*   edge_dst  = (const int*)  d_in[2];
    const int*   graph_ids = (const int*)  d_in[3];
    const float* embed     = (const float*)d_in[4];
    const float* W1        = (const float*)d_in[5];
    const float* b1        = (const float*)d_in[6];
    const float* Wpool     = (const float*)d_in[7];
    const float* bpool     = (const float*)d_in[8];
    const float* Wself     = (const float*)d_in[9];
    const float* Wneigh    = (const float*)d_in[10];
    const float* bneigh    = (const float*)d_in[11];
    const float* Wlin      = (const float*)d_in[12];
    const float* blin      = (const float*)d_in[13];
    float* out = (float*)d_out;

    const int TB = 256;
    int gridE = (NE + TB - 1) / TB;
    int gridN = (NN + TB - 1) / TB;

    k_init<<<gridN, TB>>>(out);
    k_deg<<<gridE, TB>>>(edge_src, edge_dst);
    k_scan_bsum <<<SCAN_NBLK, SCAN_BS>>>();
    k_scan_top  <<<1, SCAN_BS>>>();
    k_scan_write<<<SCAN_NBLK, SCAN_BS>>>();
    k_fill<<<gridE, TB>>>(edge_src, edge_dst);
    k_h1<<<gridN, TB>>>(tokens, embed, W1, b1, Wpool, bpool);
    k_out<<<(NN + 127) / 128, 256>>>(graph_ids, Wself, Wneigh, bneigh, Wlin, blin, out);
}

// round 6
// speedup vs baseline: 1.1513x; 1.1513x over previous
#include <cuda_runtime.h>

#define NN 500000
#define NE 1000000
#define NG 512

#define SCAN_BS 256
#define SCAN_ELEMS 2048                       // 256 threads * 8
#define SCAN_NBLK ((NN + SCAN_ELEMS - 1) / SCAN_ELEMS)   // 245

typedef unsigned long long u64;

// ---------------- scratch ----------------
__device__ int    g_cnt_out[NN];
__device__ int    g_cnt_in [NN];
__device__ float  g_ns     [NN];   // rsqrt(max(deg_out,1))
__device__ int    g_row_off[NN + 1];
__device__ int    g_cursor [NN];
__device__ int    g_csr_src[NE];
__device__ int    g_bsum [256];
__device__ int    g_bpref[256];
__device__ float4 g_h1[NN * 8];    // [N,32]
__device__ float4 g_hp[NN * 8];    // [N,32] relu(h1@Wpool+bpool)
__device__ float  g_probe_out[NG * 64];   // probe scratch (never read)

// ---------------- f32x2 helpers ----------------
__device__ __forceinline__ u64 pack2(float a) {
    u64 r;
    asm("mov.b64 %0, {%1, %1};" : "=l"(r) : "f"(a));
    return r;
}
__device__ __forceinline__ void fma2(u64& d, u64 a, u64 b) {
    asm("fma.rn.f32x2 %0, %1, %2, %0;" : "+l"(d) : "l"(a), "l"(b));
}
__device__ __forceinline__ float2 unpack2(u64 v) {
    float2 f;
    asm("mov.b64 {%0, %1}, %2;" : "=f"(f.x), "=f"(f.y) : "l"(v));
    return f;
}

// ---------------- init ----------------
__global__ void k_init(float* __restrict__ out) {
    int i = blockIdx.x * blockDim.x + threadIdx.x;
    if (i < NN) { g_cnt_out[i] = 0; g_cnt_in[i] = 0; }
    if (i < NG * 64) out[i] = 0.f;
}

// ---------------- degree counts ----------------
__global__ void k_deg(const int* __restrict__ src, const int* __restrict__ dst) {
    int e = blockIdx.x * blockDim.x + threadIdx.x;
    if (e < NE) {
        atomicAdd(&g_cnt_out[src[e]], 1);
        atomicAdd(&g_cnt_in [dst[e]], 1);
    }
}

// ---------------- scan pass 1 ----------------
__global__ __launch_bounds__(SCAN_BS) void k_scan_bsum() {
    __shared__ int sred[SCAN_BS];
    int b = blockIdx.x, t = threadIdx.x;
    int base = b * SCAN_ELEMS + t * 8;
    int s = 0;
#pragma unroll
    for (int k = 0; k < 8; k++) {
        int idx = base + k;
        if (idx < NN) s += g_cnt_in[idx];
    }
    sred[t] = s;
    __syncthreads();
    for (int o = SCAN_BS / 2; o > 0; o >>= 1) {
        if (t < o) sred[t] += sred[t + o];
        __syncthreads();
    }
    if (t == 0) g_bsum[b] = sred[0];
}

// ---------------- scan pass 2 ----------------
__global__ __launch_bounds__(SCAN_BS) void k_scan_top() {
    __shared__ int s[SCAN_BS];
    int t = threadIdx.x;
    int v = (t < SCAN_NBLK) ? g_bsum[t] : 0;
    s[t] = v;
    __syncthreads();
    for (int o = 1; o < SCAN_BS; o <<= 1) {
        int u = (t >= o) ? s[t - o] : 0;
        __syncthreads();
        s[t] += u;
        __syncthreads();
    }
    if (t < SCAN_NBLK) g_bpref[t] = s[t] - v;
    if (t == 0) g_row_off[NN] = NE;
}

// ---------------- scan pass 3 (also computes g_ns) ----------------
__global__ __launch_bounds__(SCAN_BS) void k_scan_write() {
    __shared__ int sth[SCAN_BS];
    int b = blockIdx.x, t = threadIdx.x;
    int base = b * SCAN_ELEMS + t * 8;
    int vals[8];
    int s = 0;
#pragma unroll
    for (int k = 0; k < 8; k++) {
        int idx = base + k;
        vals[k] = (idx < NN) ? g_cnt_in[idx] : 0;
        s += vals[k];
    }
    sth[t] = s;
    __syncthreads();
    int incl = s;
    for (int o = 1; o < SCAN_BS; o <<= 1) {
        int u = (t >= o) ? sth[t - o] : 0;
        __syncthreads();
        incl += u;
        sth[t] = incl;
        __syncthreads();
    }
    int run = g_bpref[b] + incl - s;
#pragma unroll
    for (int k = 0; k < 8; k++) {
        int idx = base + k;
        if (idx < NN) {
            g_row_off[idx] = run;
            g_cursor[idx] = run;
            g_ns[idx] = rsqrtf(fmaxf((float)g_cnt_out[idx], 1.0f));
        }
        run += vals[k];
    }
}

// ---------------- CSR fill ----------------
__global__ void k_fill(const int* __restrict__ src, const int* __restrict__ dst) {
    int e = blockIdx.x * blockDim.x + threadIdx.x;
    if (e < NE) {
        int p = atomicAdd(&g_cursor[dst[e]], 1);
        g_csr_src[p] = src[e];
    }
}

// ---------------- gather embed directly + MLP1 + pool MLP ----------------
__global__ __launch_bounds__(256) void k_h1(
    const int* __restrict__ tokens, const float* __restrict__ embed,
    const float* __restrict__ W1, const float* __restrict__ b1,
    const float* __restrict__ Wp, const float* __restrict__ bp)
{
    __shared__ __align__(16) u64 sW1[16 * 16], sWp[32 * 16];
    __shared__ u64 sb1[16], sbp[16];
    for (int t = threadIdx.x; t < 16 * 16; t += blockDim.x)
        ((float2*)sW1)[t] = ((const float2*)W1)[t];
    for (int t = threadIdx.x; t < 32 * 16; t += blockDim.x)
        ((float2*)sWp)[t] = ((const float2*)Wp)[t];
    for (int t = threadIdx.x; t < 16; t += blockDim.x) {
        ((float2*)sb1)[t] = ((const float2*)b1)[t];
        ((float2*)sbp)[t] = ((const float2*)bp)[t];
    }
    __syncthreads();

    int i = blockIdx.x * blockDim.x + threadIdx.x;
    if (i >= NN) return;

    int beg = g_row_off[i], end = g_row_off[i + 1];
    float4 a0 = make_float4(0, 0, 0, 0), a1 = a0, a2 = a0, a3 = a0;
    for (int e = beg; e < end; e++) {
        int s = g_csr_src[e];
        float ns = g_ns[s];
        const float4* er = (const float4*)(embed + (long)tokens[s] * 16);
        float4 v0 = er[0], v1 = er[1], v2 = er[2], v3 = er[3];
        a0.x += v0.x * ns; a0.y += v0.y * ns; a0.z += v0.z * ns; a0.w += v0.w * ns;
        a1.x += v1.x * ns; a1.y += v1.y * ns; a1.z += v1.z * ns; a1.w += v1.w * ns;
        a2.x += v2.x * ns; a2.y += v2.y * ns; a2.z += v2.z * ns; a2.w += v2.w * ns;
        a3.x += v3.x * ns; a3.y += v3.y * ns; a3.z += v3.z * ns; a3.w += v3.w * ns;
    }
    float nd = rsqrtf(fmaxf((float)(end - beg), 1.0f));
    float mr[16] = {a0.x * nd, a0.y * nd, a0.z * nd, a0.w * nd,
                    a1.x * nd, a1.y * nd, a1.z * nd, a1.w * nd,
                    a2.x * nd, a2.y * nd, a2.z * nd, a2.w * nd,
                    a3.x * nd, a3.y * nd, a3.z * nd, a3.w * nd};

    // h1 = relu(mr @ W1 + b1)
    u64 acc[16];
#pragma unroll
    for (int j = 0; j < 16; j++) acc[j] = sb1[j];
#pragma unroll
    for (int k = 0; k < 16; k++) {
        u64 av = pack2(mr[k]);
        const ulonglong2* pw = (const ulonglong2*)&sW1[k * 16];
#pragma unroll
        for (int jj = 0; jj < 8; jj++) {
            ulonglong2 w = pw[jj];
            fma2(acc[2 * jj], av, w.x);
            fma2(acc[2 * jj + 1], av, w.y);
        }
    }
    float h1f[32];
#pragma unroll
    for (int j = 0; j < 16; j++) {
        float2 f = unpack2(acc[j]);
        h1f[2 * j] = fmaxf(f.x, 0.f); h1f[2 * j + 1] = fmaxf(f.y, 0.f);
    }
#pragma unroll
    for (int k = 0; k < 8; k++)
        g_h1[i * 8 + k] = make_float4(h1f[4 * k], h1f[4 * k + 1], h1f[4 * k + 2], h1f[4 * k + 3]);

    // hp = relu(h1 @ Wpool + bpool)
    u64 pcc[16];
#pragma unroll
    for (int j = 0; j < 16; j++) pcc[j] = sbp[j];
#pragma unroll
    for (int k = 0; k < 32; k++) {
        u64 av = pack2(h1f[k]);
        const ulonglong2* pw = (const ulonglong2*)&sWp[k * 16];
#pragma unroll
        for (int jj = 0; jj < 8; jj++) {
            ulonglong2 w = pw[jj];
            fma2(pcc[2 * jj], av, w.x);
            fma2(pcc[2 * jj + 1], av, w.y);
        }
    }
#pragma unroll
    for (int j = 0; j < 8; j++) {
        float2 f0 = unpack2(pcc[2 * j]), f1 = unpack2(pcc[2 * j + 1]);
        g_hp[i * 8 + j] = make_float4(fmaxf(f0.x, 0.f), fmaxf(f0.y, 0.f),
                                      fmaxf(f1.x, 0.f), fmaxf(f1.y, 0.f));
    }
}

// ---------------- fused: gather-max + SAGE + lin + pooling ----------------
// BODY shared between the real kernel and the profiling probe.
__device__ __forceinline__ void out_body(
    const int* __restrict__ graph_ids,
    const float* __restrict__ Wself, const float* __restrict__ Wneigh,
    const float* __restrict__ bneigh,
    const float* __restrict__ Wlin, const float* __restrict__ blin,
    float* __restrict__ out)
{
    __shared__ __align__(16) u64 sWs[32 * 32], sWn[32 * 32], sWl[64 * 32];
    __shared__ u64 sbn[32], sbl[32];
    for (int t = threadIdx.x; t < 32 * 32; t += blockDim.x) {
        ((float2*)sWs)[t] = ((const float2*)Wself)[t];
        ((float2*)sWn)[t] = ((const float2*)Wneigh)[t];
    }
    for (int t = threadIdx.x; t < 64 * 32; t += blockDim.x)
        ((float2*)sWl)[t] = ((const float2*)Wlin)[t];
    for (int t = threadIdx.x; t < 32; t += blockDim.x) {
        ((float2*)sbn)[t] = ((const float2*)bneigh)[t];
        ((float2*)sbl)[t] = ((const float2*)blin)[t];
    }
    __syncthreads();

    int i = blockIdx.x * blockDim.x + threadIdx.x;
    bool valid = i < NN;
    int ic = valid ? i : NN - 1;
    int gid = graph_ids[ic];

    // gather-max of hp over incoming edges (hp >= 0; isolated -> 0 matches DGL)
    float hnf[32];
#pragma unroll
    for (int j = 0; j < 32; j++) hnf[j] = 0.f;
    int beg = g_row_off[ic], end = g_row_off[ic + 1];
    for (int e = beg; e < end; e++) {
        const float4* hr = &g_hp[(size_t)g_csr_src[e] * 8];
#pragma unroll
        for (int k = 0; k < 8; k++) {
            float4 v = hr[k];
            hnf[4 * k + 0] = fmaxf(hnf[4 * k + 0], v.x);
            hnf[4 * k + 1] = fmaxf(hnf[4 * k + 1], v.y);
            hnf[4 * k + 2] = fmaxf(hnf[4 * k + 2], v.z);
            hnf[4 * k + 3] = fmaxf(hnf[4 * k + 3], v.w);
        }
    }

    float af[32];
#pragma unroll
    for (int k = 0; k < 8; k++) {
        float4 v = g_h1[(size_t)ic * 8 + k];
        af[4 * k + 0] = v.x; af[4 * k + 1] = v.y; af[4 * k + 2] = v.z; af[4 * k + 3] = v.w;
    }

    // running packed accumulators for h3 (64 outputs)
    u64 h3acc[32];
#pragma unroll
    for (int j = 0; j < 32; j++) h3acc[j] = sbl[j];

    // h2 computed in two 32-wide halves; each half immediately folded into h3acc
#pragma unroll
    for (int half = 0; half < 2; half++) {
        u64 acc[16];
#pragma unroll
        for (int j = 0; j < 16; j++) acc[j] = sbn[half * 16 + j];
#pragma unroll
        for (int k = 0; k < 32; k++) {
            u64 av = pack2(af[k]);
            u64 bv = pack2(hnf[k]);
            const ulonglong2* ps = (const ulonglong2*)&sWs[k * 32 + half * 16];
            const ulonglong2* pn = (const ulonglong2*)&sWn[k * 32 + half * 16];
#pragma unroll
            for (int jj = 0; jj < 8; jj++) {
                ulonglong2 w = ps[jj];
                fma2(acc[2 * jj], av, w.x);
                fma2(acc[2 * jj + 1], av, w.y);
                ulonglong2 u = pn[jj];
                fma2(acc[2 * jj], bv, u.x);
                fma2(acc[2 * jj + 1], bv, u.y);
            }
        }
        float hh[32];
#pragma unroll
        for (int j = 0; j < 16; j++) {
            float2 f = unpack2(acc[j]);
            hh[2 * j] = fmaxf(f.x, 0.f); hh[2 * j + 1] = fmaxf(f.y, 0.f);
        }
#pragma unroll
        for (int k2 = 0; k2 < 32; k2++) {
            u64 av = pack2(hh[k2]);
            const ulonglong2* pl = (const ulonglong2*)&sWl[(half * 32 + k2) * 32];
#pragma unroll
            for (int jj = 0; jj < 16; jj++) {
                ulonglong2 w = pl[jj];
                fma2(h3acc[2 * jj], av, w.x);
                fma2(h3acc[2 * jj + 1], av, w.y);
            }
        }
    }

    // graph pooling: graph_ids sorted -> warps almost always uniform
    int lane = threadIdx.x & 31;
    int g0 = __shfl_sync(0xffffffffu, gid, 0);
    bool uni = __all_sync(0xffffffffu, gid == g0);
    if (uni) {
        float o0 = 0.f, o1 = 0.f;
#pragma unroll
        for (int jj = 0; jj < 32; jj++) {
            float2 f = unpack2(h3acc[jj]);
            float v0 = valid ? fmaxf(f.x, 0.f) : 0.f;
            float v1 = valid ? fmaxf(f.y, 0.f) : 0.f;
            v0 += __shfl_xor_sync(0xffffffffu, v0, 16);
            v0 += __shfl_xor_sync(0xffffffffu, v0, 8);
            v0 += __shfl_xor_sync(0xffffffffu, v0, 4);
            v0 += __shfl_xor_sync(0xffffffffu, v0, 2);
            v0 += __shfl_xor_sync(0xffffffffu, v0, 1);
            v1 += __shfl_xor_sync(0xffffffffu, v1, 16);
            v1 += __shfl_xor_sync(0xffffffffu, v1, 8);
            v1 += __shfl_xor_sync(0xffffffffu, v1, 4);
            v1 += __shfl_xor_sync(0xffffffffu, v1, 2);
            v1 += __shfl_xor_sync(0xffffffffu, v1, 1);
            int j0 = 2 * jj, j1 = 2 * jj + 1;
            if (lane == (j0 & 31)) { if (j0 < 32) o0 = v0; else o1 = v0; }
            if (lane == (j1 & 31)) { if (j1 < 32) o0 = v1; else o1 = v1; }
        }
        float* row = out + g0 * 64;
        atomicAdd(row + lane, o0);
        atomicAdd(row + 32 + lane, o1);
    } else if (valid) {
        float* row = out + gid * 64;
#pragma unroll
        for (int jj = 0; jj < 32; jj++) {
            float2 f = unpack2(h3acc[jj]);
            atomicAdd(row + 2 * jj,     fmaxf(f.x, 0.f));
            atomicAdd(row + 2 * jj + 1, fmaxf(f.y, 0.f));
        }
    }
}

__global__ __launch_bounds__(256) void k_out(
    const int* __restrict__ graph_ids,
    const float* __restrict__ Wself, const float* __restrict__ Wneigh,
    const float* __restrict__ bneigh,
    const float* __restrict__ Wlin, const float* __restrict__ blin,
    float* __restrict__ out)
{
    out_body(graph_ids, Wself, Wneigh, bneigh, Wlin, blin, out);
}

// profiling probe: identical body, scratch output, 2-wave grid.
// Reads stale-but-finite g_h1/g_hp/CSR; output never consumed.
__global__ __launch_bounds__(256) void k_out_probe(
    const int* __restrict__ graph_ids,
    const float* __restrict__ Wself, const float* __restrict__ Wneigh,
    const float* __restrict__ bneigh,
    const float* __restrict__ Wlin, const float* __restrict__ blin)
{
    out_body(graph_ids, Wself, Wneigh, bneigh, Wlin, blin, g_probe_out);
}

// ---------------- launch ----------------
extern "C" void kernel_launch(void* const* d_in, const int* in_sizes, int n_in,
                              void* d_out, int out_size) {
    const int*   tokens    = (const int*)  d_in[0];
    const int*   edge_src  = (const int*)  d_in[1];
    const int*   edge_dst  = (const int*)  d_in[2];
    const int*   graph_ids = (const int*)  d_in[3];
    const float* embed     = (const float*)d_in[4];
    const float* W1        = (const float*)d_in[5];
    const float* b1        = (const float*)d_in[6];
    const float* Wpool     = (const float*)d_in[7];
    const float* bpool     = (const float*)d_in[8];
    const float* Wself     = (const float*)d_in[9];
    const float* Wneigh    = (const float*)d_in[10];
    const float* bneigh    = (const float*)d_in[11];
    const float* Wlin      = (const float*)d_in[12];
    const float* blin      = (const float*)d_in[13];
    float* out = (float*)d_out;

    const int TB = 256;
    int gridE = (NE + TB - 1) / TB;
    int gridN = (NN + TB - 1) / TB;

    k_init<<<gridN, TB>>>(out);                                     // launch 1
    k_deg<<<gridE, TB>>>(edge_src, edge_dst);                       // launch 2
    k_scan_bsum <<<SCAN_NBLK, SCAN_BS>>>();                         // launch 3
    k_out_probe<<<296, TB>>>(graph_ids, Wself, Wneigh, bneigh,      // launch 4 (ncu slot)
                             Wlin, blin);
    k_scan_top  <<<1, SCAN_BS>>>();                                 // launch 5
    k_scan_write<<<SCAN_NBLK, SCAN_BS>>>();                         // launch 6
    k_fill<<<gridE, TB>>>(edge_src, edge_dst);                      // launch 7
    k_h1<<<gridN, TB>>>(tokens, embed, W1, b1, Wpool, bpool);       // launch 8
    k_out<<<gridN, TB>>>(graph_ids, Wself, Wneigh, bneigh, Wlin, blin, out);  // launch 9
}

// round 7
// speedup vs baseline: 1.1816x; 1.0263x over previous
#include <cuda_runtime.h>

#define NN 500000
#define NE 1000000
#define NG 512

#define SCAN_BS 256
#define SCAN_ELEMS 2048                       // 256 threads * 8
#define SCAN_NBLK ((NN + SCAN_ELEMS - 1) / SCAN_ELEMS)   // 245

typedef unsigned long long u64;

// ---------------- scratch ----------------
__device__ int    g_cnt_out[NN];
__device__ int    g_cnt_in [NN];
__device__ float  g_ns     [NN];   // rsqrt(max(deg_out,1))
__device__ int    g_row_off[NN + 1];
__device__ int    g_cursor [NN];
__device__ int    g_csr_src[NE];
__device__ int    g_bsum [256];
__device__ int    g_bpref[256];
__device__ float4 g_h1[NN * 8];    // [N,32]
__device__ float4 g_hp[NN * 8];    // [N,32] relu(h1@Wpool+bpool)
__device__ float  g_probe_out[NG * 64];   // probe scratch (never read)

// ---------------- f32x2 helpers ----------------
__device__ __forceinline__ u64 pack2(float a) {
    u64 r;
    asm("mov.b64 %0, {%1, %1};" : "=l"(r) : "f"(a));
    return r;
}
__device__ __forceinline__ void fma2(u64& d, u64 a, u64 b) {
    asm("fma.rn.f32x2 %0, %1, %2, %0;" : "+l"(d) : "l"(a), "l"(b));
}
__device__ __forceinline__ float2 unpack2(u64 v) {
    float2 f;
    asm("mov.b64 {%0, %1}, %2;" : "=f"(f.x), "=f"(f.y) : "l"(v));
    return f;
}

// ---------------- init ----------------
__global__ void k_init(float* __restrict__ out) {
    int i = blockIdx.x * blockDim.x + threadIdx.x;
    if (i < NN) { g_cnt_out[i] = 0; g_cnt_in[i] = 0; }
    if (i < NG * 64) out[i] = 0.f;
}

// ---------------- degree counts ----------------
__global__ void k_deg(const int* __restrict__ src, const int* __restrict__ dst) {
    int e = blockIdx.x * blockDim.x + threadIdx.x;
    if (e < NE) {
        atomicAdd(&g_cnt_out[src[e]], 1);
        atomicAdd(&g_cnt_in [dst[e]], 1);
    }
}

// ---------------- scan pass 1 ----------------
__global__ __launch_bounds__(SCAN_BS) void k_scan_bsum() {
    __shared__ int sred[SCAN_BS];
    int b = blockIdx.x, t = threadIdx.x;
    int base = b * SCAN_ELEMS + t * 8;
    int s = 0;
#pragma unroll
    for (int k = 0; k < 8; k++) {
        int idx = base + k;
        if (idx < NN) s += g_cnt_in[idx];
    }
    sred[t] = s;
    __syncthreads();
    for (int o = SCAN_BS / 2; o > 0; o >>= 1) {
        if (t < o) sred[t] += sred[t + o];
        __syncthreads();
    }
    if (t == 0) g_bsum[b] = sred[0];
}

// ---------------- scan pass 2 ----------------
__global__ __launch_bounds__(SCAN_BS) void k_scan_top() {
    __shared__ int s[SCAN_BS];
    int t = threadIdx.x;
    int v = (t < SCAN_NBLK) ? g_bsum[t] : 0;
    s[t] = v;
    __syncthreads();
    for (int o = 1; o < SCAN_BS; o <<= 1) {
        int u = (t >= o) ? s[t - o] : 0;
        __syncthreads();
        s[t] += u;
        __syncthreads();
    }
    if (t < SCAN_NBLK) g_bpref[t] = s[t] - v;
    if (t == 0) g_row_off[NN] = NE;
}

// ---------------- scan pass 3 (also computes g_ns) ----------------
__global__ __launch_bounds__(SCAN_BS) void k_scan_write() {
    __shared__ int sth[SCAN_BS];
    int b = blockIdx.x, t = threadIdx.x;
    int base = b * SCAN_ELEMS + t * 8;
    int vals[8];
    int s = 0;
#pragma unroll
    for (int k = 0; k < 8; k++) {
        int idx = base + k;
        vals[k] = (idx < NN) ? g_cnt_in[idx] : 0;
        s += vals[k];
    }
    sth[t] = s;
    __syncthreads();
    int incl = s;
    for (int o = 1; o < SCAN_BS; o <<= 1) {
        int u = (t >= o) ? sth[t - o] : 0;
        __syncthreads();
        incl += u;
        sth[t] = incl;
        __syncthreads();
    }
    int run = g_bpref[b] + incl - s;
#pragma unroll
    for (int k = 0; k < 8; k++) {
        int idx = base + k;
        if (idx < NN) {
            g_row_off[idx] = run;
            g_cursor[idx] = run;
            g_ns[idx] = rsqrtf(fmaxf((float)g_cnt_out[idx], 1.0f));
        }
        run += vals[k];
    }
}

// ---------------- CSR fill ----------------
__global__ void k_fill(const int* __restrict__ src, const int* __restrict__ dst) {
    int e = blockIdx.x * blockDim.x + threadIdx.x;
    if (e < NE) {
        int p = atomicAdd(&g_cursor[dst[e]], 1);
        g_csr_src[p] = src[e];
    }
}

// ---------------- gather embed directly + MLP1 + pool MLP ----------------
__global__ __launch_bounds__(256) void k_h1(
    const int* __restrict__ tokens, const float* __restrict__ embed,
    const float* __restrict__ W1, const float* __restrict__ b1,
    const float* __restrict__ Wp, const float* __restrict__ bp)
{
    __shared__ __align__(16) u64 sW1[16 * 16], sWp[32 * 16];
    __shared__ u64 sb1[16], sbp[16];
    for (int t = threadIdx.x; t < 16 * 16; t += blockDim.x)
        ((float2*)sW1)[t] = ((const float2*)W1)[t];
    for (int t = threadIdx.x; t < 32 * 16; t += blockDim.x)
        ((float2*)sWp)[t] = ((const float2*)Wp)[t];
    for (int t = threadIdx.x; t < 16; t += blockDim.x) {
        ((float2*)sb1)[t] = ((const float2*)b1)[t];
        ((float2*)sbp)[t] = ((const float2*)bp)[t];
    }
    __syncthreads();

    int i = blockIdx.x * blockDim.x + threadIdx.x;
    if (i >= NN) return;

    int beg = g_row_off[i], end = g_row_off[i + 1];
    float4 a0 = make_float4(0, 0, 0, 0), a1 = a0, a2 = a0, a3 = a0;
    for (int e = beg; e < end; e++) {
        int s = g_csr_src[e];
        float ns = g_ns[s];
        const float4* er = (const float4*)(embed + (long)tokens[s] * 16);
        float4 v0 = er[0], v1 = er[1], v2 = er[2], v3 = er[3];
        a0.x += v0.x * ns; a0.y += v0.y * ns; a0.z += v0.z * ns; a0.w += v0.w * ns;
        a1.x += v1.x * ns; a1.y += v1.y * ns; a1.z += v1.z * ns; a1.w += v1.w * ns;
        a2.x += v2.x * ns; a2.y += v2.y * ns; a2.z += v2.z * ns; a2.w += v2.w * ns;
        a3.x += v3.x * ns; a3.y += v3.y * ns; a3.z += v3.z * ns; a3.w += v3.w * ns;
    }
    float nd = rsqrtf(fmaxf((float)(end - beg), 1.0f));
    float mr[16] = {a0.x * nd, a0.y * nd, a0.z * nd, a0.w * nd,
                    a1.x * nd, a1.y * nd, a1.z * nd, a1.w * nd,
                    a2.x * nd, a2.y * nd, a2.z * nd, a2.w * nd,
                    a3.x * nd, a3.y * nd, a3.z * nd, a3.w * nd};

    // h1 = relu(mr @ W1 + b1)
    u64 acc[16];
#pragma unroll
    for (int j = 0; j < 16; j++) acc[j] = sb1[j];
#pragma unroll
    for (int k = 0; k < 16; k++) {
        u64 av = pack2(mr[k]);
        const ulonglong2* pw = (const ulonglong2*)&sW1[k * 16];
#pragma unroll
        for (int jj = 0; jj < 8; jj++) {
            ulonglong2 w = pw[jj];
            fma2(acc[2 * jj], av, w.x);
            fma2(acc[2 * jj + 1], av, w.y);
        }
    }
    float h1f[32];
#pragma unroll
    for (int j = 0; j < 16; j++) {
        float2 f = unpack2(acc[j]);
        h1f[2 * j] = fmaxf(f.x, 0.f); h1f[2 * j + 1] = fmaxf(f.y, 0.f);
    }
#pragma unroll
    for (int k = 0; k < 8; k++)
        g_h1[i * 8 + k] = make_float4(h1f[4 * k], h1f[4 * k + 1], h1f[4 * k + 2], h1f[4 * k + 3]);

    // hp = relu(h1 @ Wpool + bpool)
    u64 pcc[16];
#pragma unroll
    for (int j = 0; j < 16; j++) pcc[j] = sbp[j];
#pragma unroll
    for (int k = 0; k < 32; k++) {
        u64 av = pack2(h1f[k]);
        const ulonglong2* pw = (const ulonglong2*)&sWp[k * 16];
#pragma unroll
        for (int jj = 0; jj < 8; jj++) {
            ulonglong2 w = pw[jj];
            fma2(pcc[2 * jj], av, w.x);
            fma2(pcc[2 * jj + 1], av, w.y);
        }
    }
#pragma unroll
    for (int j = 0; j < 8; j++) {
        float2 f0 = unpack2(pcc[2 * j]), f1 = unpack2(pcc[2 * j + 1]);
        g_hp[i * 8 + j] = make_float4(fmaxf(f0.x, 0.f), fmaxf(f0.y, 0.f),
                                      fmaxf(f1.x, 0.f), fmaxf(f1.y, 0.f));
    }
}

// ---------------- fused: gather-max + SAGE + lin + pooling ----------------
// Low-register version: af/hnf/hh live in per-thread smem staging columns.
// staging layout: stag[channel * 256 + tid]  (channels 0..63) -> conflict-free LDS.
__device__ __forceinline__ void out_body(
    const int* __restrict__ graph_ids,
    const float* __restrict__ Wself, const float* __restrict__ Wneigh,
    const float* __restrict__ bneigh,
    const float* __restrict__ Wlin, const float* __restrict__ blin,
    float* __restrict__ out)
{
    __shared__ __align__(16) u64 sWs[32 * 32], sWn[32 * 32], sWl[64 * 32];
    __shared__ u64 sbn[32], sbl[32];
    extern __shared__ float stag[];   // 64 * 256 floats = 64KB dynamic

    for (int t = threadIdx.x; t < 32 * 32; t += blockDim.x) {
        ((float2*)sWs)[t] = ((const float2*)Wself)[t];
        ((float2*)sWn)[t] = ((const float2*)Wneigh)[t];
    }
    for (int t = threadIdx.x; t < 64 * 32; t += blockDim.x)
        ((float2*)sWl)[t] = ((const float2*)Wlin)[t];
    for (int t = threadIdx.x; t < 32; t += blockDim.x) {
        ((float2*)sbn)[t] = ((const float2*)bneigh)[t];
        ((float2*)sbl)[t] = ((const float2*)blin)[t];
    }
    __syncthreads();

    int tid = threadIdx.x;
    int i = blockIdx.x * 256 + tid;
    bool valid = i < NN;
    int ic = valid ? i : NN - 1;
    int gid = graph_ids[ic];

    // af (h1 row) -> staging channels 0..31
#pragma unroll
    for (int k = 0; k < 8; k++) {
        float4 v = g_h1[(size_t)ic * 8 + k];
        stag[(4 * k + 0) * 256 + tid] = v.x;
        stag[(4 * k + 1) * 256 + tid] = v.y;
        stag[(4 * k + 2) * 256 + tid] = v.z;
        stag[(4 * k + 3) * 256 + tid] = v.w;
    }

    // gather-max of hp over incoming edges (hp >= 0; isolated -> 0 matches DGL)
    {
        float hnf[32];
#pragma unroll
        for (int j = 0; j < 32; j++) hnf[j] = 0.f;
        int beg = g_row_off[ic], end = g_row_off[ic + 1];
        for (int e = beg; e < end; e++) {
            const float4* hr = &g_hp[(size_t)g_csr_src[e] * 8];
#pragma unroll
            for (int k = 0; k < 8; k++) {
                float4 v = hr[k];
                hnf[4 * k + 0] = fmaxf(hnf[4 * k + 0], v.x);
                hnf[4 * k + 1] = fmaxf(hnf[4 * k + 1], v.y);
                hnf[4 * k + 2] = fmaxf(hnf[4 * k + 2], v.z);
                hnf[4 * k + 3] = fmaxf(hnf[4 * k + 3], v.w);
            }
        }
        // hnf -> staging channels 32..63
#pragma unroll
        for (int j = 0; j < 32; j++) stag[(32 + j) * 256 + tid] = hnf[j];
    }

    // h2 = relu(af@Wself + hnf@Wneigh + bneigh): full 64-wide accumulator (32 u64)
    {
        u64 acc[32];
#pragma unroll
        for (int j = 0; j < 32; j++) acc[j] = sbn[j];
#pragma unroll
        for (int k = 0; k < 32; k++) {
            u64 av = pack2(stag[k * 256 + tid]);
            u64 bv = pack2(stag[(32 + k) * 256 + tid]);
            const ulonglong2* ps = (const ulonglong2*)&sWs[k * 32];
            const ulonglong2* pn = (const ulonglong2*)&sWn[k * 32];
#pragma unroll
            for (int jj = 0; jj < 16; jj++) {
                ulonglong2 w = ps[jj];
                fma2(acc[2 * jj], av, w.x);
                fma2(acc[2 * jj + 1], av, w.y);
                ulonglong2 u = pn[jj];
                fma2(acc[2 * jj], bv, u.x);
                fma2(acc[2 * jj + 1], bv, u.y);
            }
        }
        // relu(h2) overwrites staging channels 0..63 (af/hnf now dead)
#pragma unroll
        for (int j = 0; j < 32; j++) {
            float2 f = unpack2(acc[j]);
            stag[(2 * j) * 256 + tid]     = fmaxf(f.x, 0.f);
            stag[(2 * j + 1) * 256 + tid] = fmaxf(f.y, 0.f);
        }
    }

    // h3 = relu(h2@Wlin + blin), two 32-output halves; pooling folded per half
    int lane = tid & 31;
    int g0 = __shfl_sync(0xffffffffu, gid, 0);
    bool uni = __all_sync(0xffffffffu, gid == g0);

#pragma unroll
    for (int half = 0; half < 2; half++) {
        u64 acc2[16];
#pragma unroll
        for (int j = 0; j < 16; j++) acc2[j] = sbl[16 * half + j];
#pragma unroll
        for (int k2 = 0; k2 < 64; k2++) {
            u64 av = pack2(stag[k2 * 256 + tid]);
            const ulonglong2* pl = (const ulonglong2*)&sWl[k2 * 32 + 16 * half];
#pragma unroll
            for (int jj = 0; jj < 8; jj++) {
                ulonglong2 w = pl[jj];
                fma2(acc2[2 * jj], av, w.x);
                fma2(acc2[2 * jj + 1], av, w.y);
            }
        }
        float v[32];
#pragma unroll
        for (int j = 0; j < 16; j++) {
            float2 f = unpack2(acc2[j]);
            v[2 * j]     = valid ? fmaxf(f.x, 0.f) : 0.f;
            v[2 * j + 1] = valid ? fmaxf(f.y, 0.f) : 0.f;
        }
        if (uni) {
            float o = 0.f;
#pragma unroll
            for (int j = 0; j < 32; j++) {
                float x = v[j];
                x += __shfl_xor_sync(0xffffffffu, x, 16);
                x += __shfl_xor_sync(0xffffffffu, x, 8);
                x += __shfl_xor_sync(0xffffffffu, x, 4);
                x += __shfl_xor_sync(0xffffffffu, x, 2);
                x += __shfl_xor_sync(0xffffffffu, x, 1);
                if (lane == j) o = x;
            }
            atomicAdd(out + g0 * 64 + 32 * half + lane, o);
        } else if (valid) {
            float* row = out + gid * 64 + 32 * half;
#pragma unroll
            for (int j = 0; j < 32; j++) atomicAdd(row + j, v[j]);
        }
    }
}

__global__ __launch_bounds__(256, 2) void k_out(
    const int* __restrict__ graph_ids,
    const float* __restrict__ Wself, const float* __restrict__ Wneigh,
    const float* __restrict__ bneigh,
    const float* __restrict__ Wlin, const float* __restrict__ blin,
    float* __restrict__ out)
{
    out_body(graph_ids, Wself, Wneigh, bneigh, Wlin, blin, out);
}

// profiling probe: identical body, scratch output, 1 full wave at 2 CTA/SM.
__global__ __launch_bounds__(256, 2) void k_out_probe(
    const int* __restrict__ graph_ids,
    const float* __restrict__ Wself, const float* __restrict__ Wneigh,
    const float* __restrict__ bneigh,
    const float* __restrict__ Wlin, const float* __restrict__ blin)
{
    out_body(graph_ids, Wself, Wneigh, bneigh, Wlin, blin, g_probe_out);
}

// ---------------- launch ----------------
extern "C" void kernel_launch(void* const* d_in, const int* in_sizes, int n_in,
                              void* d_out, int out_size) {
    const int*   tokens    = (const int*)  d_in[0];
    const int*   edge_src  = (const int*)  d_in[1];
    const int*   edge_dst  = (const int*)  d_in[2];
    const int*   graph_ids = (const int*)  d_in[3];
    const float* embed     = (const float*)d_in[4];
    const float* W1        = (const float*)d_in[5];
    const float* b1        = (const float*)d_in[6];
    const float* Wpool     = (const float*)d_in[7];
    const float* bpool     = (const float*)d_in[8];
    const float* Wself     = (const float*)d_in[9];
    const float* Wneigh    = (const float*)d_in[10];
    const float* bneigh    = (const float*)d_in[11];
    const float* Wlin      = (const float*)d_in[12];
    const float* blin      = (const float*)d_in[13];
    float* out = (float*)d_out;

    const int STAG_BYTES = 64 * 256 * 4;   // 64KB dynamic staging
    cudaFuncSetAttribute(k_out,       cudaFuncAttributeMaxDynamicSharedMemorySize, STAG_BYTES);
    cudaFuncSetAttribute(k_out_probe, cudaFuncAttributeMaxDynamicSharedMemorySize, STAG_BYTES);

    const int TB = 256;
    int gridE = (NE + TB - 1) / TB;
    int gridN = (NN + TB - 1) / TB;

    k_init<<<gridN, TB>>>(out);                                     // launch 1
    k_deg<<<gridE, TB>>>(edge_src, edge_dst);                       // launch 2
    k_scan_bsum <<<SCAN_NBLK, SCAN_BS>>>();                         // launch 3
    k_out_probe<<<296, TB, STAG_BYTES>>>(graph_ids, Wself, Wneigh,  // launch 4 (ncu slot)
                                         bneigh, Wlin, blin);
    k_scan_top  <<<1, SCAN_BS>>>();                                 // launch 5
    k_scan_write<<<SCAN_NBLK, SCAN_BS>>>();                         // launch 6
    k_fill<<<gridE, TB>>>(edge_src, edge_dst);                      // launch 7
    k_h1<<<gridN, TB>>>(tokens, embed, W1, b1, Wpool, bpool);       // launch 8
    k_out<<<gridN, TB, STAG_BYTES>>>(graph_ids, Wself, Wneigh, bneigh, Wlin, blin, out);  // launch 9
}